// round 1
// baseline (speedup 1.0000x reference)
#include <cuda_runtime.h>

#define NN 50000
#define DD 128
#define EMAX 600000

// ------------- scratch (static device globals; no allocation) -------------
__device__ float g_H[NN * DD];     // GEMM output, pre-scaled by dinv[row]
__device__ float g_X[NN * DD];     // layer activations
__device__ float g_dinv[NN];
__device__ int   g_cnt[NN];
__device__ int   g_rowptr[NN + 1];
__device__ int   g_cursor[NN];
__device__ int   g_srcs[EMAX];
__device__ int   g_flag;           // 1 => edge_index is int32, 0 => int64

// --------------------------- preprocessing --------------------------------
__global__ void k_zero() {
    int i = blockIdx.x * blockDim.x + threadIdx.x;
    if (i < NN) g_cnt[i] = 0;
    if (i == 0) g_flag = 0;
}

// If the buffer is int64 (values < 50000, non-negative), every odd 32-bit
// word is a zero high-half. For int32 data the odd words are random values
// in [0, 50000) — essentially surely nonzero somewhere in 600k samples.
// Index bound 2*i+1 < 2*E is in-bounds for both layouts.
__global__ void k_detect(const unsigned int* __restrict__ words, int E) {
    int i = blockIdx.x * blockDim.x + threadIdx.x;
    if (i < E) {
        if (words[2 * i + 1] != 0u) g_flag = 1;
    }
}

__global__ void k_hist(const void* __restrict__ edges, int E) {
    int is32 = g_flag;
    int e = blockIdx.x * blockDim.x + threadIdx.x;
    if (e < E) {
        int dst = is32 ? ((const int*)edges)[E + e]
                       : (int)((const long long*)edges)[E + e];
        atomicAdd(&g_cnt[dst], 1);
    }
}

__global__ void k_dinv() {
    int i = blockIdx.x * blockDim.x + threadIdx.x;
    if (i < NN) g_dinv[i] = rsqrtf((float)(g_cnt[i] + 1));  // +1 self-loop
}

// Single-block exclusive scan of g_cnt -> g_rowptr (and g_cursor copy).
__global__ void k_scan() {
    __shared__ int warpsums[32];
    __shared__ int running;
    int tid = threadIdx.x;
    if (tid == 0) running = 0;
    __syncthreads();
    for (int base = 0; base < NN; base += 1024) {
        int i = base + tid;
        int v = (i < NN) ? g_cnt[i] : 0;
        int x = v;
        #pragma unroll
        for (int o = 1; o < 32; o <<= 1) {
            int y = __shfl_up_sync(0xffffffffu, x, o);
            if ((tid & 31) >= o) x += y;
        }
        if ((tid & 31) == 31) warpsums[tid >> 5] = x;
        __syncthreads();
        if (tid < 32) {
            int w = warpsums[tid];
            #pragma unroll
            for (int o = 1; o < 32; o <<= 1) {
                int y = __shfl_up_sync(0xffffffffu, w, o);
                if (tid >= o) w += y;
            }
            warpsums[tid] = w;
        }
        __syncthreads();
        int excl = running + (x - v) + ((tid >= 32) ? warpsums[(tid >> 5) - 1] : 0);
        if (i < NN) { g_rowptr[i] = excl; g_cursor[i] = excl; }
        __syncthreads();
        if (tid == 0) running += warpsums[31];
        __syncthreads();
    }
    if (tid == 0) g_rowptr[NN] = running;
}

__global__ void k_fill(const void* __restrict__ edges, int E) {
    int is32 = g_flag;
    int e = blockIdx.x * blockDim.x + threadIdx.x;
    if (e < E) {
        int src, dst;
        if (is32) {
            src = ((const int*)edges)[e];
            dst = ((const int*)edges)[E + e];
        } else {
            src = (int)((const long long*)edges)[e];
            dst = (int)((const long long*)edges)[E + e];
        }
        int pos = atomicAdd(&g_cursor[dst], 1);
        g_srcs[pos] = src;
    }
}

// ------------------------------ GEMM ---------------------------------------
// H[row] = dinv[row] * (X[row] @ W).  BM=64, BN=128(full), BK=16,
// 256 threads, each computes 8x4 outputs.
__global__ void k_gemm(const float* __restrict__ Xext, const float* __restrict__ W) {
    const float* __restrict__ X = Xext ? Xext : g_X;
    __shared__ float Xs[64][16];
    __shared__ float Ws[16][128];

    int tx = threadIdx.x & 31;  // 0..31 -> 4 cols each
    int ty = threadIdx.x >> 5;  // 0..7  -> 8 rows each
    int row0 = blockIdx.x * 64;

    float acc[8][4];
    #pragma unroll
    for (int i = 0; i < 8; i++)
        #pragma unroll
        for (int j = 0; j < 4; j++) acc[i][j] = 0.0f;

    for (int k0 = 0; k0 < DD; k0 += 16) {
        // load Xs: 64x16 = 1024 floats, one float4 per thread
        {
            int t = threadIdx.x;
            int r = t >> 2;          // 0..63
            int c4 = t & 3;          // 0..3
            int grow = row0 + r;
            float4 v = (grow < NN) ? *(const float4*)&X[grow * DD + k0 + c4 * 4]
                                   : make_float4(0.f, 0.f, 0.f, 0.f);
            *(float4*)&Xs[r][c4 * 4] = v;
        }
        // load Ws: 16x128 = 512 float4, two per thread
        {
            #pragma unroll
            for (int q = 0; q < 2; q++) {
                int idx = threadIdx.x + q * 256;  // 0..511
                int r = idx >> 5;                 // 0..15
                int c4 = idx & 31;
                *(float4*)&Ws[r][c4 * 4] = *(const float4*)&W[(k0 + r) * DD + c4 * 4];
            }
        }
        __syncthreads();
        #pragma unroll
        for (int kk = 0; kk < 16; kk++) {
            float4 wv = *(const float4*)&Ws[kk][tx * 4];
            float xv[8];
            #pragma unroll
            for (int i = 0; i < 8; i++) xv[i] = Xs[ty * 8 + i][kk];
            #pragma unroll
            for (int i = 0; i < 8; i++) {
                acc[i][0] += xv[i] * wv.x;
                acc[i][1] += xv[i] * wv.y;
                acc[i][2] += xv[i] * wv.z;
                acc[i][3] += xv[i] * wv.w;
            }
        }
        __syncthreads();
    }

    #pragma unroll
    for (int i = 0; i < 8; i++) {
        int grow = row0 + ty * 8 + i;
        if (grow < NN) {
            float s = g_dinv[grow];
            float4 o = make_float4(acc[i][0] * s, acc[i][1] * s,
                                   acc[i][2] * s, acc[i][3] * s);
            *(float4*)&g_H[grow * DD + tx * 4] = o;
        }
    }
}

// --------------------------- aggregation -----------------------------------
// One warp per node, float4 per lane (128 floats / 32 lanes).
// out[i] = relu?( dinv[i] * (G[i] + sum_{e in CSR(i)} G[src_e]) + b )
__global__ void k_agg(const float* __restrict__ bias, float* __restrict__ outExt,
                      int do_relu, int zero0) {
    int gid = blockIdx.x * blockDim.x + threadIdx.x;
    int i = gid >> 5;
    int lane = gid & 31;
    if (i >= NN) return;

    const float4* __restrict__ G = (const float4*)g_H;
    float4* __restrict__ out = outExt ? (float4*)outExt : (float4*)g_X;

    float4 acc = G[i * 32 + lane];  // self-loop term (G already scaled by dinv[src])
    int e = g_rowptr[i];
    int end = g_rowptr[i + 1];
    for (; e + 4 <= end; e += 4) {
        int s0 = g_srcs[e], s1 = g_srcs[e + 1], s2 = g_srcs[e + 2], s3 = g_srcs[e + 3];
        float4 a = G[s0 * 32 + lane];
        float4 b = G[s1 * 32 + lane];
        float4 c = G[s2 * 32 + lane];
        float4 d = G[s3 * 32 + lane];
        acc.x += (a.x + b.x) + (c.x + d.x);
        acc.y += (a.y + b.y) + (c.y + d.y);
        acc.z += (a.z + b.z) + (c.z + d.z);
        acc.w += (a.w + b.w) + (c.w + d.w);
    }
    for (; e < end; e++) {
        int s = g_srcs[e];
        float4 a = G[s * 32 + lane];
        acc.x += a.x; acc.y += a.y; acc.z += a.z; acc.w += a.w;
    }

    float di = g_dinv[i];
    float4 b4 = ((const float4*)bias)[lane];
    float4 o;
    o.x = acc.x * di + b4.x;
    o.y = acc.y * di + b4.y;
    o.z = acc.z * di + b4.z;
    o.w = acc.w * di + b4.w;
    if (do_relu) {
        o.x = fmaxf(o.x, 0.f); o.y = fmaxf(o.y, 0.f);
        o.z = fmaxf(o.z, 0.f); o.w = fmaxf(o.w, 0.f);
    }
    if (zero0 && i == 0) o = make_float4(0.f, 0.f, 0.f, 0.f);
    out[i * 32 + lane] = o;
}

// ------------------------------- launch -------------------------------------
extern "C" void kernel_launch(void* const* d_in, const int* in_sizes, int n_in,
                              void* d_out, int out_size) {
    const float* emb = (const float*)d_in[0];
    const float* W1  = (const float*)d_in[1];
    const float* b1  = (const float*)d_in[2];
    const float* W2  = (const float*)d_in[3];
    const float* b2  = (const float*)d_in[4];
    const float* W3  = (const float*)d_in[5];
    const float* b3  = (const float*)d_in[6];
    const void*  edges = d_in[7];

    int E = in_sizes[7] / 2;
    if (E > EMAX) E = EMAX;

    const int TB = 256;
    int nBlk = (NN + TB - 1) / TB;
    int eBlk = (E + TB - 1) / TB;

    k_zero<<<nBlk, TB>>>();
    k_detect<<<eBlk, TB>>>((const unsigned int*)edges, E);
    k_hist<<<eBlk, TB>>>(edges, E);
    k_dinv<<<nBlk, TB>>>();
    k_scan<<<1, 1024>>>();
    k_fill<<<eBlk, TB>>>(edges, E);

    dim3 gemmGrid((NN + 63) / 64);
    int aggBlocks = (NN * 32 + TB - 1) / TB;

    // layer 1
    k_gemm<<<gemmGrid, TB>>>(emb, W1);
    k_agg<<<aggBlocks, TB>>>(b1, nullptr, 1, 0);
    // layer 2
    k_gemm<<<gemmGrid, TB>>>(nullptr, W2);
    k_agg<<<aggBlocks, TB>>>(b2, nullptr, 1, 0);
    // layer 3 (no relu, zero row 0, write d_out)
    k_gemm<<<gemmGrid, TB>>>(nullptr, W3);
    k_agg<<<aggBlocks, TB>>>(b3, (float*)d_out, 0, 1);
}

// round 2
// speedup vs baseline: 1.2858x; 1.2858x over previous
#include <cuda_runtime.h>
#include <cuda_bf16.h>

#define NN 50000
#define DD 128
#define EMAX 600000

// ------------- scratch (static device globals; no allocation) -------------
__device__ float g_H[NN * DD];     // GEMM output, pre-scaled by dinv[row]
__device__ float g_X[NN * DD];     // layer activations
__device__ float g_dinv[NN];
__device__ int   g_cnt[NN];
__device__ int   g_rowptr[NN + 1];
__device__ int   g_cursor[NN];
__device__ int   g_srcs[EMAX];
__device__ int   g_flag;           // 1 => edge_index is int32, 0 => int64

// --------------------------- preprocessing --------------------------------
__global__ void k_zero() {
    int i = blockIdx.x * blockDim.x + threadIdx.x;
    if (i < NN) g_cnt[i] = 0;
    if (i == 0) g_flag = 0;
}

__global__ void k_detect(const unsigned int* __restrict__ words, int E) {
    int i = blockIdx.x * blockDim.x + threadIdx.x;
    if (i < E) {
        if (words[2 * i + 1] != 0u) g_flag = 1;
    }
}

__global__ void k_hist(const void* __restrict__ edges, int E) {
    int is32 = g_flag;
    int e = blockIdx.x * blockDim.x + threadIdx.x;
    if (e < E) {
        int dst = is32 ? ((const int*)edges)[E + e]
                       : (int)((const long long*)edges)[E + e];
        atomicAdd(&g_cnt[dst], 1);
    }
}

__global__ void k_dinv() {
    int i = blockIdx.x * blockDim.x + threadIdx.x;
    if (i < NN) g_dinv[i] = rsqrtf((float)(g_cnt[i] + 1));  // +1 self-loop
}

__global__ void k_scan() {
    __shared__ int warpsums[32];
    __shared__ int running;
    int tid = threadIdx.x;
    if (tid == 0) running = 0;
    __syncthreads();
    for (int base = 0; base < NN; base += 1024) {
        int i = base + tid;
        int v = (i < NN) ? g_cnt[i] : 0;
        int x = v;
        #pragma unroll
        for (int o = 1; o < 32; o <<= 1) {
            int y = __shfl_up_sync(0xffffffffu, x, o);
            if ((tid & 31) >= o) x += y;
        }
        if ((tid & 31) == 31) warpsums[tid >> 5] = x;
        __syncthreads();
        if (tid < 32) {
            int w = warpsums[tid];
            #pragma unroll
            for (int o = 1; o < 32; o <<= 1) {
                int y = __shfl_up_sync(0xffffffffu, w, o);
                if (tid >= o) w += y;
            }
            warpsums[tid] = w;
        }
        __syncthreads();
        int excl = running + (x - v) + ((tid >= 32) ? warpsums[(tid >> 5) - 1] : 0);
        if (i < NN) { g_rowptr[i] = excl; g_cursor[i] = excl; }
        __syncthreads();
        if (tid == 0) running += warpsums[31];
        __syncthreads();
    }
    if (tid == 0) g_rowptr[NN] = running;
}

__global__ void k_fill(const void* __restrict__ edges, int E) {
    int is32 = g_flag;
    int e = blockIdx.x * blockDim.x + threadIdx.x;
    if (e < E) {
        int src, dst;
        if (is32) {
            src = ((const int*)edges)[e];
            dst = ((const int*)edges)[E + e];
        } else {
            src = (int)((const long long*)edges)[e];
            dst = (int)((const long long*)edges)[E + e];
        }
        int pos = atomicAdd(&g_cursor[dst], 1);
        g_srcs[pos] = src;
    }
}

// ------------------------------ tensor-core GEMM ----------------------------
// H[row] = dinv[row] * (X[row] @ W), fp32-accurate via 2-way bf16 split
// (x = hi + lo) with 3 MMA passes: hh + hl + lh (ll dropped, ~2^-18 rel).
// Block: 128 rows x 128 cols x K=128 fully resident in smem.
// 8 warps arranged 4(row) x 2(col): warp tile = 32 rows x 64 cols.

#define LDS_PAD 136   // 128 + 8 bf16 elements per smem row (conflict-free ldmatrix)

__device__ __forceinline__ void cvt4_split(float4 v, unsigned int hi[2], unsigned int lo[2]) {
    float f[4] = {v.x, v.y, v.z, v.w};
    unsigned short h[4], l[4];
    #pragma unroll
    for (int i = 0; i < 4; i++) {
        __nv_bfloat16 b = __float2bfloat16(f[i]);
        h[i] = __bfloat16_as_ushort(b);
        float r = f[i] - __bfloat162float(b);
        l[i] = __bfloat16_as_ushort(__float2bfloat16(r));
    }
    hi[0] = (unsigned int)h[0] | ((unsigned int)h[1] << 16);
    hi[1] = (unsigned int)h[2] | ((unsigned int)h[3] << 16);
    lo[0] = (unsigned int)l[0] | ((unsigned int)l[1] << 16);
    lo[1] = (unsigned int)l[2] | ((unsigned int)l[3] << 16);
}

__device__ __forceinline__ void ldm_x4(unsigned int r[4], const unsigned short* p) {
    unsigned int addr = (unsigned int)__cvta_generic_to_shared(p);
    asm volatile("ldmatrix.sync.aligned.m8n8.x4.shared.b16 {%0,%1,%2,%3}, [%4];"
                 : "=r"(r[0]), "=r"(r[1]), "=r"(r[2]), "=r"(r[3]) : "r"(addr));
}

__device__ __forceinline__ void ldm_x4_t(unsigned int r[4], const unsigned short* p) {
    unsigned int addr = (unsigned int)__cvta_generic_to_shared(p);
    asm volatile("ldmatrix.sync.aligned.m8n8.x4.trans.shared.b16 {%0,%1,%2,%3}, [%4];"
                 : "=r"(r[0]), "=r"(r[1]), "=r"(r[2]), "=r"(r[3]) : "r"(addr));
}

__device__ __forceinline__ void mma16816(float c[4], const unsigned int a[4],
                                         unsigned int b0, unsigned int b1) {
    asm volatile(
        "mma.sync.aligned.m16n8k16.row.col.f32.bf16.bf16.f32 "
        "{%0,%1,%2,%3}, {%4,%5,%6,%7}, {%8,%9}, {%0,%1,%2,%3};"
        : "+f"(c[0]), "+f"(c[1]), "+f"(c[2]), "+f"(c[3])
        : "r"(a[0]), "r"(a[1]), "r"(a[2]), "r"(a[3]), "r"(b0), "r"(b1));
}

__global__ void __launch_bounds__(256, 1)
k_gemm_mma(const float* __restrict__ Xext, const float* __restrict__ W) {
    extern __shared__ unsigned short sm[];
    unsigned short* Ah = sm;
    unsigned short* Al = Ah + 128 * LDS_PAD;
    unsigned short* Bh = Al + 128 * LDS_PAD;
    unsigned short* Bl = Bh + 128 * LDS_PAD;

    const float* __restrict__ X = Xext ? Xext : g_X;
    int row0 = blockIdx.x * 128;
    int t = threadIdx.x;

    // load + split-convert W [128 x 128] (k-major rows)
    #pragma unroll
    for (int it = 0; it < 16; it++) {
        int idx = t + it * 256;
        int r = idx >> 5, c4 = idx & 31;
        float4 v = *(const float4*)&W[r * DD + c4 * 4];
        unsigned int hi[2], lo[2];
        cvt4_split(v, hi, lo);
        ((uint2*)(Bh + r * LDS_PAD + c4 * 4))[0] = make_uint2(hi[0], hi[1]);
        ((uint2*)(Bl + r * LDS_PAD + c4 * 4))[0] = make_uint2(lo[0], lo[1]);
    }
    // load + split-convert X tile [128 x 128]
    #pragma unroll
    for (int it = 0; it < 16; it++) {
        int idx = t + it * 256;
        int r = idx >> 5, c4 = idx & 31;
        int grow = row0 + r;
        float4 v = (grow < NN) ? *(const float4*)&X[grow * DD + c4 * 4]
                               : make_float4(0.f, 0.f, 0.f, 0.f);
        unsigned int hi[2], lo[2];
        cvt4_split(v, hi, lo);
        ((uint2*)(Ah + r * LDS_PAD + c4 * 4))[0] = make_uint2(hi[0], hi[1]);
        ((uint2*)(Al + r * LDS_PAD + c4 * 4))[0] = make_uint2(lo[0], lo[1]);
    }
    __syncthreads();

    int lane = t & 31, w = t >> 5;
    int wr = w >> 1, wc = w & 1;
    int arow = wr * 32;       // warp's row base within tile
    int bcol = wc * 64;       // warp's col base
    int r8 = lane & 7, sub = lane >> 3;

    float acc[2][8][4];
    #pragma unroll
    for (int mi = 0; mi < 2; mi++)
        #pragma unroll
        for (int nj = 0; nj < 8; nj++)
            #pragma unroll
            for (int q = 0; q < 4; q++) acc[mi][nj][q] = 0.f;

    #pragma unroll 2
    for (int ks = 0; ks < 8; ks++) {
        unsigned int ah[2][4], al[2][4], bh[4][4], bl[4][4];
        #pragma unroll
        for (int mi = 0; mi < 2; mi++) {
            int off = (arow + mi * 16 + (sub & 1) * 8 + r8) * LDS_PAD
                      + ks * 16 + (sub >> 1) * 8;
            ldm_x4(ah[mi], Ah + off);
            ldm_x4(al[mi], Al + off);
        }
        #pragma unroll
        for (int ni = 0; ni < 4; ni++) {
            int off = (ks * 16 + (sub & 1) * 8 + r8) * LDS_PAD
                      + bcol + ni * 16 + (sub >> 1) * 8;
            ldm_x4_t(bh[ni], Bh + off);
            ldm_x4_t(bl[ni], Bl + off);
        }
        #pragma unroll
        for (int mi = 0; mi < 2; mi++) {
            #pragma unroll
            for (int nj = 0; nj < 8; nj++) {
                int ni = nj >> 1, o = (nj & 1) * 2;
                mma16816(acc[mi][nj], ah[mi], bh[ni][o], bh[ni][o + 1]);  // hi*hi
                mma16816(acc[mi][nj], ah[mi], bl[ni][o], bl[ni][o + 1]);  // hi*lo
                mma16816(acc[mi][nj], al[mi], bh[ni][o], bh[ni][o + 1]);  // lo*hi
            }
        }
    }

    // epilogue: scale by dinv[row], store to g_H
    #pragma unroll
    for (int mi = 0; mi < 2; mi++) {
        int rA = row0 + arow + mi * 16 + (lane >> 2);
        int rB = rA + 8;
        float sA = (rA < NN) ? g_dinv[rA] : 0.f;
        float sB = (rB < NN) ? g_dinv[rB] : 0.f;
        #pragma unroll
        for (int nj = 0; nj < 8; nj++) {
            int col = bcol + nj * 8 + (lane & 3) * 2;
            if (rA < NN)
                *(float2*)&g_H[rA * DD + col] =
                    make_float2(acc[mi][nj][0] * sA, acc[mi][nj][1] * sA);
            if (rB < NN)
                *(float2*)&g_H[rB * DD + col] =
                    make_float2(acc[mi][nj][2] * sB, acc[mi][nj][3] * sB);
        }
    }
}

// --------------------------- aggregation -----------------------------------
__global__ void k_agg(const float* __restrict__ bias, float* __restrict__ outExt,
                      int do_relu, int zero0) {
    int gid = blockIdx.x * blockDim.x + threadIdx.x;
    int i = gid >> 5;
    int lane = gid & 31;
    if (i >= NN) return;

    const float4* __restrict__ G = (const float4*)g_H;
    float4* __restrict__ out = outExt ? (float4*)outExt : (float4*)g_X;

    float4 acc = G[i * 32 + lane];  // self-loop term (G already scaled by dinv[src])
    int e = g_rowptr[i];
    int end = g_rowptr[i + 1];
    for (; e + 4 <= end; e += 4) {
        int s0 = g_srcs[e], s1 = g_srcs[e + 1], s2 = g_srcs[e + 2], s3 = g_srcs[e + 3];
        float4 a = G[s0 * 32 + lane];
        float4 b = G[s1 * 32 + lane];
        float4 c = G[s2 * 32 + lane];
        float4 d = G[s3 * 32 + lane];
        acc.x += (a.x + b.x) + (c.x + d.x);
        acc.y += (a.y + b.y) + (c.y + d.y);
        acc.z += (a.z + b.z) + (c.z + d.z);
        acc.w += (a.w + b.w) + (c.w + d.w);
    }
    for (; e < end; e++) {
        int s = g_srcs[e];
        float4 a = G[s * 32 + lane];
        acc.x += a.x; acc.y += a.y; acc.z += a.z; acc.w += a.w;
    }

    float di = g_dinv[i];
    float4 b4 = ((const float4*)bias)[lane];
    float4 o;
    o.x = acc.x * di + b4.x;
    o.y = acc.y * di + b4.y;
    o.z = acc.z * di + b4.z;
    o.w = acc.w * di + b4.w;
    if (do_relu) {
        o.x = fmaxf(o.x, 0.f); o.y = fmaxf(o.y, 0.f);
        o.z = fmaxf(o.z, 0.f); o.w = fmaxf(o.w, 0.f);
    }
    if (zero0 && i == 0) o = make_float4(0.f, 0.f, 0.f, 0.f);
    out[i * 32 + lane] = o;
}

// ------------------------------- launch -------------------------------------
extern "C" void kernel_launch(void* const* d_in, const int* in_sizes, int n_in,
                              void* d_out, int out_size) {
    const float* emb = (const float*)d_in[0];
    const float* W1  = (const float*)d_in[1];
    const float* b1  = (const float*)d_in[2];
    const float* W2  = (const float*)d_in[3];
    const float* b2  = (const float*)d_in[4];
    const float* W3  = (const float*)d_in[5];
    const float* b3  = (const float*)d_in[6];
    const void*  edges = d_in[7];

    int E = in_sizes[7] / 2;
    if (E > EMAX) E = EMAX;

    const int TB = 256;
    int nBlk = (NN + TB - 1) / TB;
    int eBlk = (E + TB - 1) / TB;

    const int GEMM_SMEM = 4 * 128 * LDS_PAD * 2;  // 139264 bytes
    cudaFuncSetAttribute(k_gemm_mma, cudaFuncAttributeMaxDynamicSharedMemorySize,
                         GEMM_SMEM);

    k_zero<<<nBlk, TB>>>();
    k_detect<<<eBlk, TB>>>((const unsigned int*)edges, E);
    k_hist<<<eBlk, TB>>>(edges, E);
    k_dinv<<<nBlk, TB>>>();
    k_scan<<<1, 1024>>>();
    k_fill<<<eBlk, TB>>>(edges, E);

    dim3 gemmGrid((NN + 127) / 128);
    int aggBlocks = (NN * 32 + TB - 1) / TB;

    // layer 1
    k_gemm_mma<<<gemmGrid, TB, GEMM_SMEM>>>(emb, W1);
    k_agg<<<aggBlocks, TB>>>(b1, nullptr, 1, 0);
    // layer 2
    k_gemm_mma<<<gemmGrid, TB, GEMM_SMEM>>>(nullptr, W2);
    k_agg<<<aggBlocks, TB>>>(b2, nullptr, 1, 0);
    // layer 3 (no relu, zero row 0, write d_out)
    k_gemm_mma<<<gemmGrid, TB, GEMM_SMEM>>>(nullptr, W3);
    k_agg<<<aggBlocks, TB>>>(b3, (float*)d_out, 0, 1);
}